// round 1
// baseline (speedup 1.0000x reference)
#include <cuda_runtime.h>
#include <math.h>

// Problem constants (fixed by the problem instance)
#define B_   8
#define S_   4096
#define D_   1024
#define M_   32
#define R_   (B_*S_)      // 32768 rows of X
#define NC_  64           // scan chunks
#define CHUNK_ 64         // steps per chunk (NC_*CHUNK_ == S_)

// -------- device scratch (no runtime allocation allowed) --------
__device__ float g_r [R_*M_];     // sigmoid read gates
__device__ float g_w [R_*M_];     // sigmoid write gates
__device__ float g_nm[R_*M_];     // new_mem
__device__ float g_q [R_*M_];     // r * mem_state
__device__ float g_wq[M_*D_];     // Wp @ Wo_m
__device__ float g_cvec[D_];      // bp @ Wo_m + bo
__device__ float g_cA[B_*NC_*M_]; // per-chunk affine A
__device__ float g_cB[B_*NC_*M_]; // per-chunk affine B
__device__ float g_ms[B_*NC_*M_]; // mem state at chunk start

// ============================================================
// K1: gates GEMM  (32768 x 1024) @ (1024 x 96) fused sigmoid
// BM=64, BN=96, BK=16, 256 threads, 4x6 microtile
// ============================================================
__global__ void __launch_bounds__(256) k1_rwm(
    const float* __restrict__ X,
    const float* __restrict__ Wr, const float* __restrict__ br,
    const float* __restrict__ Ww, const float* __restrict__ bw,
    const float* __restrict__ Wm, const float* __restrict__ bm)
{
    __shared__ float Xs[16][64];
    __shared__ float Ws[16][96];
    const int t = threadIdx.x;
    const int rowBase = blockIdx.x * 64;
    const int tx = t & 15;       // n direction
    const int ty = t >> 4;       // row direction
    const int n0 = tx * 6;
    const int r0 = ty * 4;

    float acc[4][6];
#pragma unroll
    for (int i = 0; i < 4; i++)
#pragma unroll
        for (int j = 0; j < 6; j++) acc[i][j] = 0.f;

    const int lrow = t >> 2;     // 0..63
    const int lseg = t & 3;      // 0..3  (float4 within 16 k's)

    for (int k0 = 0; k0 < D_; k0 += 16) {
        float4 xv = *reinterpret_cast<const float4*>(
            &X[(size_t)(rowBase + lrow) * D_ + k0 + lseg * 4]);
        Xs[lseg*4+0][lrow] = xv.x;
        Xs[lseg*4+1][lrow] = xv.y;
        Xs[lseg*4+2][lrow] = xv.z;
        Xs[lseg*4+3][lrow] = xv.w;
#pragma unroll
        for (int u = 0; u < 6; u++) {
            int idx = t + u * 256;           // 0..1535
            int k = idx / 96, n = idx % 96;
            float v;
            if (n < 32)      v = Wr[(k0 + k) * M_ + n];
            else if (n < 64) v = Ww[(k0 + k) * M_ + (n - 32)];
            else             v = Wm[(k0 + k) * M_ + (n - 64)];
            Ws[k][n] = v;
        }
        __syncthreads();
#pragma unroll
        for (int kk = 0; kk < 16; kk++) {
            float4 av = *reinterpret_cast<const float4*>(&Xs[kk][r0]);
            float a[4] = {av.x, av.y, av.z, av.w};
            float2 b0 = *reinterpret_cast<const float2*>(&Ws[kk][n0]);
            float2 b1 = *reinterpret_cast<const float2*>(&Ws[kk][n0 + 2]);
            float2 b2 = *reinterpret_cast<const float2*>(&Ws[kk][n0 + 4]);
            float b[6] = {b0.x, b0.y, b1.x, b1.y, b2.x, b2.y};
#pragma unroll
            for (int i = 0; i < 4; i++)
#pragma unroll
                for (int j = 0; j < 6; j++)
                    acc[i][j] += a[i] * b[j];
        }
        __syncthreads();
    }

#pragma unroll
    for (int i = 0; i < 4; i++) {
        int row = rowBase + r0 + i;
#pragma unroll
        for (int j = 0; j < 6; j++) {
            int n = n0 + j;
            float v = acc[i][j];
            if (n < 32) {
                v += br[n];
                g_r[(size_t)row * M_ + n] = 1.f / (1.f + expf(-v));
            } else if (n < 64) {
                v += bw[n - 32];
                g_w[(size_t)row * M_ + (n - 32)] = 1.f / (1.f + expf(-v));
            } else {
                v += bm[n - 64];
                g_nm[(size_t)row * M_ + (n - 64)] = v;
            }
        }
    }
}

// ============================================================
// K2: Wq = Wp @ Wo_m   (32x1024) @ (1024x1024)
// 8 blocks x 256 threads; each block does 128 output cols
// ============================================================
__global__ void __launch_bounds__(256) k2_wq(
    const float* __restrict__ Wp, const float* __restrict__ Wo)
{
    __shared__ float Ps[32][128];
    const int t = threadIdx.x;
    const int e = blockIdx.x * 128 + (t & 127);
    const int mg = t >> 7;   // 0 or 1 -> rows [mg*16, mg*16+16)
    float acc[16];
#pragma unroll
    for (int i = 0; i < 16; i++) acc[i] = 0.f;

    for (int d0 = 0; d0 < D_; d0 += 128) {
#pragma unroll
        for (int u = 0; u < 16; u++) {
            int idx = t + u * 256;
            int m = idx >> 7, dd = idx & 127;
            Ps[m][dd] = Wp[m * D_ + d0 + dd];
        }
        __syncthreads();
        for (int dd = 0; dd < 128; dd++) {
            float wo = Wo[(size_t)(D_ + d0 + dd) * D_ + e];
#pragma unroll
            for (int i = 0; i < 16; i++)
                acc[i] += Ps[mg * 16 + i][dd] * wo;
        }
        __syncthreads();
    }
#pragma unroll
    for (int i = 0; i < 16; i++)
        g_wq[(mg * 16 + i) * D_ + e] = acc[i];
}

// cvec = bp @ Wo_m + bo
__global__ void k2_cvec(
    const float* __restrict__ bp, const float* __restrict__ Wo,
    const float* __restrict__ bo)
{
    int e = blockIdx.x * 256 + threadIdx.x;
    float acc = bo[e];
    for (int d = 0; d < D_; d++)
        acc += bp[d] * Wo[(size_t)(D_ + d) * D_ + e];
    g_cvec[e] = acc;
}

// ============================================================
// K3: chunked parallel scan of mem[t+1] = (1-w)*mem + w*nm
// ============================================================
__global__ void __launch_bounds__(256) k3a_chunk()
{
    int g = blockIdx.x * 256 + threadIdx.x;  // 16384 threads
    int m = g & 31;
    int c = (g >> 5) & (NC_ - 1);
    int b = g >> 11;
    size_t base = ((size_t)b * S_ + (size_t)c * CHUNK_) * M_ + m;
    float A = 1.f, Bc = 0.f;
    for (int i = 0; i < CHUNK_; i++) {
        size_t idx = base + (size_t)i * M_;
        float wv = g_w[idx];
        float a = 1.f - wv;
        A = a * A;
        Bc = a * Bc + wv * g_nm[idx];
    }
    g_cA[g] = A;
    g_cB[g] = Bc;
}

__global__ void k3b_prefix()
{
    int t = threadIdx.x;        // 256 = B*M
    int b = t >> 5, m = t & 31;
    float mem = 0.f;
    for (int c = 0; c < NC_; c++) {
        int gi = (b * NC_ + c) * 32 + m;
        g_ms[gi] = mem;
        mem = g_cA[gi] * mem + g_cB[gi];
    }
}

__global__ void __launch_bounds__(256) k3c_emit()
{
    int g = blockIdx.x * 256 + threadIdx.x;
    int m = g & 31;
    int c = (g >> 5) & (NC_ - 1);
    int b = g >> 11;
    size_t base = ((size_t)b * S_ + (size_t)c * CHUNK_) * M_ + m;
    float mem = g_ms[g];
    for (int i = 0; i < CHUNK_; i++) {
        size_t idx = base + (size_t)i * M_;
        float rv = g_r[idx];
        float wv = g_w[idx];
        float nv = g_nm[idx];
        g_q[idx] = rv * mem;                 // value used at step s (pre-update)
        mem = (1.f - wv) * mem + wv * nv;
    }
}

// ============================================================
// K4: fused output GEMM
// out(32768,1024) = tanh( X@Wo_x + Q@Wq + cvec ), K = 1024 + 32
// BM=128, BN=128, BK=8, 256 threads, 8x8 microtile (split 4+4)
// ============================================================
__global__ void __launch_bounds__(256) k4_gemm(
    const float* __restrict__ X,
    const float* __restrict__ Wo,
    float* __restrict__ out)
{
    __shared__ float As[8][128];
    __shared__ float Bs[8][128];
    const int t = threadIdx.x;
    const int rowBase = blockIdx.y * 128;
    const int e0 = blockIdx.x * 128;
    const int tx = t & 15;       // n
    const int ty = t >> 4;       // m

    float acc[8][8];
#pragma unroll
    for (int i = 0; i < 8; i++)
#pragma unroll
        for (int j = 0; j < 8; j++) acc[i][j] = 0.f;

    const int arow = t >> 1;     // 0..127
    const int aseg = t & 1;      // float4 index within 8 k's
    const int bk   = t >> 5;     // 0..7
    const int bseg = t & 31;     // float4 index within 128 cols

    for (int k0 = 0; k0 < 1056; k0 += 8) {
        float4 av, bv;
        if (k0 < 1024) {
            av = *reinterpret_cast<const float4*>(
                &X[(size_t)(rowBase + arow) * D_ + k0 + aseg * 4]);
            bv = *reinterpret_cast<const float4*>(
                &Wo[(size_t)(k0 + bk) * D_ + e0 + bseg * 4]);
        } else {
            av = *reinterpret_cast<const float4*>(
                &g_q[(size_t)(rowBase + arow) * M_ + (k0 - 1024) + aseg * 4]);
            bv = *reinterpret_cast<const float4*>(
                &g_wq[(size_t)(k0 - 1024 + bk) * D_ + e0 + bseg * 4]);
        }
        As[aseg*4+0][arow] = av.x;
        As[aseg*4+1][arow] = av.y;
        As[aseg*4+2][arow] = av.z;
        As[aseg*4+3][arow] = av.w;
        *reinterpret_cast<float4*>(&Bs[bk][bseg * 4]) = bv;
        __syncthreads();

#pragma unroll
        for (int kk = 0; kk < 8; kk++) {
            float4 a0 = *reinterpret_cast<const float4*>(&As[kk][ty * 4]);
            float4 a1 = *reinterpret_cast<const float4*>(&As[kk][64 + ty * 4]);
            float4 b0 = *reinterpret_cast<const float4*>(&Bs[kk][tx * 4]);
            float4 b1 = *reinterpret_cast<const float4*>(&Bs[kk][64 + tx * 4]);
            float a[8] = {a0.x, a0.y, a0.z, a0.w, a1.x, a1.y, a1.z, a1.w};
            float b[8] = {b0.x, b0.y, b0.z, b0.w, b1.x, b1.y, b1.z, b1.w};
#pragma unroll
            for (int i = 0; i < 8; i++)
#pragma unroll
                for (int j = 0; j < 8; j++)
                    acc[i][j] += a[i] * b[j];
        }
        __syncthreads();
    }

    // epilogue: + cvec, tanh, vectorized stores
    float4 cv0 = *reinterpret_cast<const float4*>(&g_cvec[e0 + tx * 4]);
    float4 cv1 = *reinterpret_cast<const float4*>(&g_cvec[e0 + 64 + tx * 4]);
    float cv[8] = {cv0.x, cv0.y, cv0.z, cv0.w, cv1.x, cv1.y, cv1.z, cv1.w};
#pragma unroll
    for (int i = 0; i < 8; i++) {
        int row = rowBase + ((i < 4) ? (ty * 4 + i) : (64 + ty * 4 + i - 4));
        float4 o0, o1;
        o0.x = tanhf(acc[i][0] + cv[0]);
        o0.y = tanhf(acc[i][1] + cv[1]);
        o0.z = tanhf(acc[i][2] + cv[2]);
        o0.w = tanhf(acc[i][3] + cv[3]);
        o1.x = tanhf(acc[i][4] + cv[4]);
        o1.y = tanhf(acc[i][5] + cv[5]);
        o1.z = tanhf(acc[i][6] + cv[6]);
        o1.w = tanhf(acc[i][7] + cv[7]);
        *reinterpret_cast<float4*>(&out[(size_t)row * D_ + e0 + tx * 4]) = o0;
        *reinterpret_cast<float4*>(&out[(size_t)row * D_ + e0 + 64 + tx * 4]) = o1;
    }
}

// ============================================================
// launch
// ============================================================
extern "C" void kernel_launch(void* const* d_in, const int* in_sizes, int n_in,
                              void* d_out, int out_size)
{
    const float* x  = (const float*)d_in[0];
    const float* Wr = (const float*)d_in[1];
    const float* br = (const float*)d_in[2];
    const float* Ww = (const float*)d_in[3];
    const float* bw = (const float*)d_in[4];
    const float* Wm = (const float*)d_in[5];
    const float* bm = (const float*)d_in[6];
    const float* Wp = (const float*)d_in[7];
    const float* bp = (const float*)d_in[8];
    const float* Wo = (const float*)d_in[9];
    const float* bo = (const float*)d_in[10];
    float* out = (float*)d_out;

    // 1) gate/new_mem GEMMs (independent of everything else)
    k1_rwm<<<R_ / 64, 256>>>(x, Wr, br, Ww, bw, Wm, bm);

    // 2) folded weights (independent of K1; same stream so order is fine)
    k2_wq<<<8, 256>>>(Wp, Wo);
    k2_cvec<<<4, 256>>>(bp, Wo, bo);

    // 3) linear-recurrence scan (chunked parallel scan)
    k3a_chunk<<<(B_ * M_ * NC_) / 256, 256>>>();
    k3b_prefix<<<1, 256>>>();
    k3c_emit<<<(B_ * M_ * NC_) / 256, 256>>>();

    // 4) fused output GEMM + tanh
    dim3 grid4(D_ / 128, R_ / 128);
    k4_gemm<<<grid4, 256>>>(x, Wo, out);
}

// round 4
// speedup vs baseline: 1.7964x; 1.7964x over previous
#include <cuda_runtime.h>
#include <cuda_bf16.h>
#include <math.h>

typedef unsigned int u32;

// Problem constants
#define B_   8
#define S_   4096
#define D_   1024
#define M_   32
#define R_   (B_*S_)      // 32768 rows
#define NC_  64
#define CHUNK_ 64

// -------- device scratch --------
__device__ float g_r [R_*M_];
__device__ float g_w [R_*M_];
__device__ float g_nm[R_*M_];
__device__ float g_q [R_*M_];
__device__ float g_wq[M_*D_];     // Wp @ Wo_m
__device__ float g_cvec[D_];
__device__ float g_cA[B_*NC_*M_];
__device__ float g_cB[B_*NC_*M_];
__device__ float g_ms[B_*NC_*M_];

// ---------------- mma / ldmatrix helpers ----------------
__device__ __forceinline__ void mma16816(float* c, const u32* a, const u32* b) {
    asm volatile(
        "mma.sync.aligned.m16n8k16.row.col.f32.bf16.bf16.f32 "
        "{%0,%1,%2,%3},{%4,%5,%6,%7},{%8,%9},{%0,%1,%2,%3};\n"
        : "+f"(c[0]), "+f"(c[1]), "+f"(c[2]), "+f"(c[3])
        : "r"(a[0]), "r"(a[1]), "r"(a[2]), "r"(a[3]), "r"(b[0]), "r"(b[1]));
}
__device__ __forceinline__ void ldsm_x4(u32* r, u32 addr) {
    asm volatile("ldmatrix.sync.aligned.m8n8.x4.shared.b16 {%0,%1,%2,%3},[%4];"
        : "=r"(r[0]), "=r"(r[1]), "=r"(r[2]), "=r"(r[3]) : "r"(addr));
}
__device__ __forceinline__ void ldsm_x2t(u32* r, u32 addr) {
    asm volatile("ldmatrix.sync.aligned.m8n8.x2.trans.shared.b16 {%0,%1},[%2];"
        : "=r"(r[0]), "=r"(r[1]) : "r"(addr));
}
__device__ __forceinline__ void split2(float x, float y, u32& hi, u32& lo) {
    __nv_bfloat16 hx = __float2bfloat16(x);
    __nv_bfloat16 hy = __float2bfloat16(y);
    __nv_bfloat16 lx = __float2bfloat16(x - __bfloat162float(hx));
    __nv_bfloat16 ly = __float2bfloat16(y - __bfloat162float(hy));
    __nv_bfloat162 h2; h2.x = hx; h2.y = hy;
    __nv_bfloat162 l2; l2.x = lx; l2.y = ly;
    hi = *reinterpret_cast<u32*>(&h2);
    lo = *reinterpret_cast<u32*>(&l2);
}

// ---------- shared memory layouts ----------
#define APAD 40           // bf16 per A smem row (128 rows x 32 k)
#define A_BYTES 10240     // 128*40*2

#define BPAD1 104         // bf16 per B smem row (k1: 32 k x 96 n)
#define K1_AH 0
#define K1_AL 10240
#define K1_BH 20480
#define K1_BL 27136
#define STG1  33792       // total k1 smem bytes

#define BPAD4 136         // bf16 per B smem row (k4: 32 k x 128 n)
#define K4_AH 0
#define K4_AL 10240
#define K4_BH 20480
#define K4_BL 29184
#define STG4  37888       // total k4 smem bytes

// ============================================================
// K1 stage load/store helpers
// ============================================================
__device__ __forceinline__ void k1_load(
    const float* __restrict__ X,
    const float* __restrict__ Wr, const float* __restrict__ Ww,
    const float* __restrict__ Wm,
    int rowBase, int t, int k0, float4* aReg, float4* bReg)
{
#pragma unroll
    for (int u = 0; u < 4; u++) {
        int idx = t + u * 256;
        int row = idx >> 3;
        int c4 = idx & 7;
        aReg[u] = *reinterpret_cast<const float4*>(
            X + (size_t)(rowBase + row) * D_ + k0 + c4 * 4);
    }
#pragma unroll
    for (int u = 0; u < 3; u++) {
        int idx = t + u * 256;
        int row = idx / 24;
        int c4 = idx % 24;
        const float* src;
        if (c4 < 8)       src = Wr + (size_t)(k0 + row) * M_ + c4 * 4;
        else if (c4 < 16) src = Ww + (size_t)(k0 + row) * M_ + (c4 - 8) * 4;
        else              src = Wm + (size_t)(k0 + row) * M_ + (c4 - 16) * 4;
        bReg[u] = *reinterpret_cast<const float4*>(src);
    }
}

__device__ __forceinline__ void k1_store(
    char* base, int t, const float4* aReg, const float4* bReg)
{
#pragma unroll
    for (int u = 0; u < 4; u++) {
        int idx = t + u * 256;
        int row = idx >> 3;
        int koff = (idx & 7) * 4;
        u32 h0, l0, h1, l1;
        split2(aReg[u].x, aReg[u].y, h0, l0);
        split2(aReg[u].z, aReg[u].w, h1, l1);
        u32 off = (u32)(row * APAD + koff) * 2;
        *reinterpret_cast<u32*>(base + K1_AH + off)     = h0;
        *reinterpret_cast<u32*>(base + K1_AH + off + 4) = h1;
        *reinterpret_cast<u32*>(base + K1_AL + off)     = l0;
        *reinterpret_cast<u32*>(base + K1_AL + off + 4) = l1;
    }
#pragma unroll
    for (int u = 0; u < 3; u++) {
        int idx = t + u * 256;
        int row = idx / 24;
        int noff = (idx % 24) * 4;
        u32 h0, l0, h1, l1;
        split2(bReg[u].x, bReg[u].y, h0, l0);
        split2(bReg[u].z, bReg[u].w, h1, l1);
        u32 off = (u32)(row * BPAD1 + noff) * 2;
        *reinterpret_cast<u32*>(base + K1_BH + off)     = h0;
        *reinterpret_cast<u32*>(base + K1_BH + off + 4) = h1;
        *reinterpret_cast<u32*>(base + K1_BL + off)     = l0;
        *reinterpret_cast<u32*>(base + K1_BL + off + 4) = l1;
    }
}

// ============================================================
// K1: gates GEMM (32768 x 96) = X @ [Wr|Ww|Wm], tensor cores
// ============================================================
__global__ void __launch_bounds__(256) k1_rwm(
    const float* __restrict__ X,
    const float* __restrict__ Wr, const float* __restrict__ br,
    const float* __restrict__ Ww, const float* __restrict__ bw,
    const float* __restrict__ Wm, const float* __restrict__ bm)
{
    __shared__ __align__(16) char sm1[STG1];
    const int t = threadIdx.x;
    const int rowBase = blockIdx.x * 128;
    const int wid = t >> 5;
    const int lane = t & 31;
    const int wm = wid >> 1;
    const int wn = wid & 1;
    const u32 smBase = (u32)__cvta_generic_to_shared(sm1);

    float acc[2][6][4];
#pragma unroll
    for (int i = 0; i < 2; i++) {
#pragma unroll
        for (int j = 0; j < 6; j++) {
#pragma unroll
            for (int kq = 0; kq < 4; kq++) acc[i][j][kq] = 0.f;
        }
    }

    float4 aReg[4];
    float4 bReg[3];
    k1_load(X, Wr, Ww, Wm, rowBase, t, 0, aReg, bReg);
    k1_store(sm1, t, aReg, bReg);
    __syncthreads();

    const int NS = D_ / 32;
    for (int s = 0; s < NS; s++) {
        if (s + 1 < NS) k1_load(X, Wr, Ww, Wm, rowBase, t, (s + 1) * 32, aReg, bReg);
#pragma unroll
        for (int kh = 0; kh < 2; kh++) {
            int kk = kh * 16;
            u32 ah[2][4];
            u32 al[2][4];
#pragma unroll
            for (int mt = 0; mt < 2; mt++) {
                int r = wm * 32 + mt * 16 + (lane & 15);
                int kc = kk + ((lane >> 4) << 3);
                ldsm_x4(ah[mt], smBase + K1_AH + (r * APAD + kc) * 2);
                ldsm_x4(al[mt], smBase + K1_AL + (r * APAD + kc) * 2);
            }
            int krow = kk + (lane & 7) + ((lane >> 3) & 1) * 8;
#pragma unroll
            for (int nt = 0; nt < 6; nt++) {
                int nn = wn * 48 + nt * 8;
                u32 bh[2];
                u32 bl[2];
                ldsm_x2t(bh, smBase + K1_BH + (krow * BPAD1 + nn) * 2);
                ldsm_x2t(bl, smBase + K1_BL + (krow * BPAD1 + nn) * 2);
#pragma unroll
                for (int mt = 0; mt < 2; mt++) {
                    mma16816(acc[mt][nt], ah[mt], bh);
                    mma16816(acc[mt][nt], ah[mt], bl);
                    mma16816(acc[mt][nt], al[mt], bh);
                }
            }
        }
        __syncthreads();
        if (s + 1 < NS) k1_store(sm1, t, aReg, bReg);
        __syncthreads();
    }

    // epilogue: bias + sigmoid, scatter to g_r/g_w/g_nm
#pragma unroll
    for (int mt = 0; mt < 2; mt++) {
#pragma unroll
        for (int nt = 0; nt < 6; nt++) {
            int n = wn * 48 + nt * 8 + (lane & 3) * 2;
            int row0 = rowBase + wm * 32 + mt * 16 + (lane >> 2);
#pragma unroll
            for (int half = 0; half < 2; half++) {
                int row = row0 + half * 8;
                float v0 = acc[mt][nt][half * 2 + 0];
                float v1 = acc[mt][nt][half * 2 + 1];
                float2 o;
                if (n < 32) {
                    o.x = 1.f / (1.f + expf(-(v0 + br[n])));
                    o.y = 1.f / (1.f + expf(-(v1 + br[n + 1])));
                    *reinterpret_cast<float2*>(&g_r[(size_t)row * M_ + n]) = o;
                } else if (n < 64) {
                    o.x = 1.f / (1.f + expf(-(v0 + bw[n - 32])));
                    o.y = 1.f / (1.f + expf(-(v1 + bw[n - 31])));
                    *reinterpret_cast<float2*>(&g_w[(size_t)row * M_ + n - 32]) = o;
                } else {
                    o.x = v0 + bm[n - 64];
                    o.y = v1 + bm[n - 63];
                    *reinterpret_cast<float2*>(&g_nm[(size_t)row * M_ + n - 64]) = o;
                }
            }
        }
    }
}

// ============================================================
// K2: Wq = Wp @ Wo_m  (32x1024)@(1024x1024)
// ============================================================
__global__ void __launch_bounds__(256) k2_wq(
    const float* __restrict__ Wp, const float* __restrict__ Wo)
{
    __shared__ float Ps[32][128];
    const int t = threadIdx.x;
    const int e = blockIdx.x * 128 + (t & 127);
    const int mg = t >> 7;
    float acc[16];
#pragma unroll
    for (int i = 0; i < 16; i++) acc[i] = 0.f;

    for (int d0 = 0; d0 < D_; d0 += 128) {
#pragma unroll
        for (int u = 0; u < 16; u++) {
            int idx = t + u * 256;
            Ps[idx >> 7][idx & 127] = Wp[(idx >> 7) * D_ + d0 + (idx & 127)];
        }
        __syncthreads();
        for (int dd = 0; dd < 128; dd++) {
            float wo = Wo[(size_t)(D_ + d0 + dd) * D_ + e];
#pragma unroll
            for (int i = 0; i < 16; i++)
                acc[i] += Ps[mg * 16 + i][dd] * wo;
        }
        __syncthreads();
    }
#pragma unroll
    for (int i = 0; i < 16; i++)
        g_wq[(mg * 16 + i) * D_ + e] = acc[i];
}

__global__ void k2_cvec(
    const float* __restrict__ bp, const float* __restrict__ Wo,
    const float* __restrict__ bo)
{
    int e = blockIdx.x * 256 + threadIdx.x;
    float acc = bo[e];
    for (int d = 0; d < D_; d++)
        acc += bp[d] * Wo[(size_t)(D_ + d) * D_ + e];
    g_cvec[e] = acc;
}

// ============================================================
// K3: chunked parallel scan of mem[t+1] = (1-w)*mem + w*nm
// ============================================================
__global__ void __launch_bounds__(256) k3a_chunk()
{
    int g = blockIdx.x * 256 + threadIdx.x;
    int m = g & 31;
    int c = (g >> 5) & (NC_ - 1);
    int b = g >> 11;
    size_t base = ((size_t)b * S_ + (size_t)c * CHUNK_) * M_ + m;
    float A = 1.f;
    float Bc = 0.f;
    for (int i = 0; i < CHUNK_; i++) {
        size_t idx = base + (size_t)i * M_;
        float wv = g_w[idx];
        float a = 1.f - wv;
        A = a * A;
        Bc = a * Bc + wv * g_nm[idx];
    }
    g_cA[g] = A;
    g_cB[g] = Bc;
}

__global__ void k3b_prefix()
{
    int t = threadIdx.x;
    int b = t >> 5;
    int m = t & 31;
    float mem = 0.f;
    for (int c = 0; c < NC_; c++) {
        int gi = (b * NC_ + c) * 32 + m;
        g_ms[gi] = mem;
        mem = g_cA[gi] * mem + g_cB[gi];
    }
}

__global__ void __launch_bounds__(256) k3c_emit()
{
    int g = blockIdx.x * 256 + threadIdx.x;
    int m = g & 31;
    int c = (g >> 5) & (NC_ - 1);
    int b = g >> 11;
    size_t base = ((size_t)b * S_ + (size_t)c * CHUNK_) * M_ + m;
    float mem = g_ms[g];
    for (int i = 0; i < CHUNK_; i++) {
        size_t idx = base + (size_t)i * M_;
        float rv = g_r[idx];
        float wv = g_w[idx];
        float nv = g_nm[idx];
        g_q[idx] = rv * mem;
        mem = (1.f - wv) * mem + wv * nv;
    }
}

// ============================================================
// K4 stage load/store helpers
// ============================================================
__device__ __forceinline__ void k4_load(
    const float* __restrict__ X, const float* __restrict__ Wo,
    int rowBase, int e0, int t, int k0, float4* aReg, float4* bReg)
{
#pragma unroll
    for (int u = 0; u < 4; u++) {
        int idx = t + u * 256;
        int row = idx >> 3;
        int c4 = idx & 7;
        const float* asrc;
        if (k0 < 1024) asrc = X + (size_t)(rowBase + row) * D_ + k0 + c4 * 4;
        else           asrc = g_q + (size_t)(rowBase + row) * M_ + c4 * 4;
        aReg[u] = *reinterpret_cast<const float4*>(asrc);
        int brow = idx >> 5;
        int bc4 = idx & 31;
        const float* bsrc;
        if (k0 < 1024) bsrc = Wo + (size_t)(k0 + brow) * D_ + e0 + bc4 * 4;
        else           bsrc = g_wq + (size_t)brow * D_ + e0 + bc4 * 4;
        bReg[u] = *reinterpret_cast<const float4*>(bsrc);
    }
}

__device__ __forceinline__ void k4_store(
    char* base, int t, const float4* aReg, const float4* bReg)
{
#pragma unroll
    for (int u = 0; u < 4; u++) {
        int idx = t + u * 256;
        int row = idx >> 3;
        int koff = (idx & 7) * 4;
        u32 h0, l0, h1, l1;
        split2(aReg[u].x, aReg[u].y, h0, l0);
        split2(aReg[u].z, aReg[u].w, h1, l1);
        u32 off = (u32)(row * APAD + koff) * 2;
        *reinterpret_cast<u32*>(base + K4_AH + off)     = h0;
        *reinterpret_cast<u32*>(base + K4_AH + off + 4) = h1;
        *reinterpret_cast<u32*>(base + K4_AL + off)     = l0;
        *reinterpret_cast<u32*>(base + K4_AL + off + 4) = l1;
        int brow = idx >> 5;
        int noff = (idx & 31) * 4;
        split2(bReg[u].x, bReg[u].y, h0, l0);
        split2(bReg[u].z, bReg[u].w, h1, l1);
        u32 boff = (u32)(brow * BPAD4 + noff) * 2;
        *reinterpret_cast<u32*>(base + K4_BH + boff)     = h0;
        *reinterpret_cast<u32*>(base + K4_BH + boff + 4) = h1;
        *reinterpret_cast<u32*>(base + K4_BL + boff)     = l0;
        *reinterpret_cast<u32*>(base + K4_BL + boff + 4) = l1;
    }
}

// ============================================================
// K4: out(32768,1024) = tanh([X|Q] @ [[Wo_x],[Wq]] + cvec), K=1056
// ============================================================
__global__ void __launch_bounds__(256) k4_gemm(
    const float* __restrict__ X,
    const float* __restrict__ Wo,
    float* __restrict__ out)
{
    __shared__ __align__(16) char sm4[STG4];
    const int t = threadIdx.x;
    const int rowBase = blockIdx.y * 128;
    const int e0 = blockIdx.x * 128;
    const int wid = t >> 5;
    const int lane = t & 31;
    const int wm = wid >> 1;
    const int wn = wid & 1;
    const u32 smBase = (u32)__cvta_generic_to_shared(sm4);

    float acc[2][8][4];
#pragma unroll
    for (int i = 0; i < 2; i++) {
#pragma unroll
        for (int j = 0; j < 8; j++) {
#pragma unroll
            for (int kq = 0; kq < 4; kq++) acc[i][j][kq] = 0.f;
        }
    }

    float4 aReg[4];
    float4 bReg[4];
    k4_load(X, Wo, rowBase, e0, t, 0, aReg, bReg);
    k4_store(sm4, t, aReg, bReg);
    __syncthreads();

    const int NS = 33;  // K = 1056
    for (int s = 0; s < NS; s++) {
        if (s + 1 < NS) k4_load(X, Wo, rowBase, e0, t, (s + 1) * 32, aReg, bReg);
#pragma unroll
        for (int kh = 0; kh < 2; kh++) {
            int kk = kh * 16;
            u32 ah[2][4];
            u32 al[2][4];
#pragma unroll
            for (int mt = 0; mt < 2; mt++) {
                int r = wm * 32 + mt * 16 + (lane & 15);
                int kc = kk + ((lane >> 4) << 3);
                ldsm_x4(ah[mt], smBase + K4_AH + (r * APAD + kc) * 2);
                ldsm_x4(al[mt], smBase + K4_AL + (r * APAD + kc) * 2);
            }
            int krow = kk + (lane & 7) + ((lane >> 3) & 1) * 8;
#pragma unroll
            for (int nt = 0; nt < 8; nt++) {
                int nn = wn * 64 + nt * 8;
                u32 bh[2];
                u32 bl[2];
                ldsm_x2t(bh, smBase + K4_BH + (krow * BPAD4 + nn) * 2);
                ldsm_x2t(bl, smBase + K4_BL + (krow * BPAD4 + nn) * 2);
#pragma unroll
                for (int mt = 0; mt < 2; mt++) {
                    mma16816(acc[mt][nt], ah[mt], bh);
                    mma16816(acc[mt][nt], ah[mt], bl);
                    mma16816(acc[mt][nt], al[mt], bh);
                }
            }
        }
        __syncthreads();
        if (s + 1 < NS) k4_store(sm4, t, aReg, bReg);
        __syncthreads();
    }

    // epilogue: + cvec, tanh
#pragma unroll
    for (int mt = 0; mt < 2; mt++) {
#pragma unroll
        for (int nt = 0; nt < 8; nt++) {
            int col = e0 + wn * 64 + nt * 8 + (lane & 3) * 2;
            float cv0 = g_cvec[col];
            float cv1 = g_cvec[col + 1];
            int row0 = rowBase + wm * 32 + mt * 16 + (lane >> 2);
#pragma unroll
            for (int half = 0; half < 2; half++) {
                int row = row0 + half * 8;
                float2 o;
                o.x = tanhf(acc[mt][nt][half * 2 + 0] + cv0);
                o.y = tanhf(acc[mt][nt][half * 2 + 1] + cv1);
                *reinterpret_cast<float2*>(&out[(size_t)row * D_ + col]) = o;
            }
        }
    }
}

// ============================================================
// launch
// ============================================================
extern "C" void kernel_launch(void* const* d_in, const int* in_sizes, int n_in,
                              void* d_out, int out_size)
{
    const float* x  = (const float*)d_in[0];
    const float* Wr = (const float*)d_in[1];
    const float* br = (const float*)d_in[2];
    const float* Ww = (const float*)d_in[3];
    const float* bw = (const float*)d_in[4];
    const float* Wm = (const float*)d_in[5];
    const float* bm = (const float*)d_in[6];
    const float* Wp = (const float*)d_in[7];
    const float* bp = (const float*)d_in[8];
    const float* Wo = (const float*)d_in[9];
    const float* bo = (const float*)d_in[10];
    float* out = (float*)d_out;

    // 1) gates GEMM (tensor cores, bf16 hi/lo split)
    k1_rwm<<<R_ / 128, 256>>>(x, Wr, br, Ww, bw, Wm, bm);

    // 2) folded weights
    k2_wq<<<8, 256>>>(Wp, Wo);
    k2_cvec<<<4, 256>>>(bp, Wo, bo);

    // 3) linear-recurrence scan
    k3a_chunk<<<(B_ * M_ * NC_) / 256, 256>>>();
    k3b_prefix<<<1, 256>>>();
    k3c_emit<<<(B_ * M_ * NC_) / 256, 256>>>();

    // 4) fused output GEMM + tanh (tensor cores, bf16 hi/lo split)
    dim3 grid4(D_ / 128, R_ / 128);
    k4_gemm<<<grid4, 256>>>(x, Wo, out);
}

// round 5
// speedup vs baseline: 3.0952x; 1.7230x over previous
#include <cuda_runtime.h>
#include <cuda_fp16.h>
#include <math.h>

typedef unsigned int u32;

// Problem constants
#define B_   8
#define S_   4096
#define D_   1024
#define M_   32
#define R_   (B_*S_)      // 32768 rows
#define NC_  64
#define CHUNK_ 64

// -------- device scratch --------
__device__ float  g_r [R_*M_];
__device__ float  g_w [R_*M_];
__device__ float  g_nm[R_*M_];
__device__ float  g_wq[M_*D_];       // Wp @ Wo_m (f32)
__device__ float  g_cvec[D_];
__device__ float  g_cA[B_*NC_*M_];
__device__ float  g_cB[B_*NC_*M_];
__device__ float  g_ms[B_*NC_*M_];
__device__ __half g_xh [R_*D_];      // fp16 X
__device__ __half g_qh [R_*M_];      // fp16 Q = r*mem
__device__ __half g_woh[D_*D_];      // fp16 Wo_x
__device__ __half g_wqh[M_*D_];      // fp16 Wq
__device__ __half g_wg [D_*96];      // fp16 packed [Wr|Ww|Wm]

// ---------------- mma / ldmatrix / cp.async helpers ----------------
__device__ __forceinline__ void mma_f16(float* c, const u32* a, const u32* b) {
    asm volatile(
        "mma.sync.aligned.m16n8k16.row.col.f32.f16.f16.f32 "
        "{%0,%1,%2,%3},{%4,%5,%6,%7},{%8,%9},{%0,%1,%2,%3};\n"
        : "+f"(c[0]), "+f"(c[1]), "+f"(c[2]), "+f"(c[3])
        : "r"(a[0]), "r"(a[1]), "r"(a[2]), "r"(a[3]), "r"(b[0]), "r"(b[1]));
}
__device__ __forceinline__ void ldsm_x4(u32* r, u32 addr) {
    asm volatile("ldmatrix.sync.aligned.m8n8.x4.shared.b16 {%0,%1,%2,%3},[%4];"
        : "=r"(r[0]), "=r"(r[1]), "=r"(r[2]), "=r"(r[3]) : "r"(addr));
}
__device__ __forceinline__ void ldsm_x2t(u32* r, u32 addr) {
    asm volatile("ldmatrix.sync.aligned.m8n8.x2.trans.shared.b16 {%0,%1},[%2];"
        : "=r"(r[0]), "=r"(r[1]) : "r"(addr));
}
__device__ __forceinline__ void cpa16(u32 saddr, const void* gptr) {
    asm volatile("cp.async.cg.shared.global [%0], [%1], 16;" :: "r"(saddr), "l"(gptr));
}
__device__ __forceinline__ void cpa_commit() {
    asm volatile("cp.async.commit_group;");
}
__device__ __forceinline__ void cpa_wait1() {
    asm volatile("cp.async.wait_group 1;");
}
__device__ __forceinline__ void cpa_wait0() {
    asm volatile("cp.async.wait_group 0;");
}

// ---------- shared memory layouts (fp16, single precision pass) ----------
// A tile: 128 rows x 32 k, row = 40 halves (80B, 16B-aligned chunks)
// K4 B tile: 32 k-rows x 128 n, row = 136 halves (272B)
// K1 B tile: 32 k-rows x 96 n,  row = 104 halves (208B)
#define APADH   40
#define A_BYT   10240      // 128*80
#define B4PADH  136
#define B4_BYT  8704       // 32*272
#define B1PADH  104
#define B1_BYT  6656       // 32*208
#define STG4    18944      // A_BYT + B4_BYT
#define STG1    16896      // A_BYT + B1_BYT

// ============================================================
// K0: conversion kernels
// ============================================================
__global__ void __launch_bounds__(256) k0_f2h(
    const float* __restrict__ src, __half* __restrict__ dst)
{
    int i = blockIdx.x * 256 + threadIdx.x;     // one float4 per thread
    float4 v = *reinterpret_cast<const float4*>(src + (size_t)i * 4);
    __half2 h0 = __floats2half2_rn(v.x, v.y);
    __half2 h1 = __floats2half2_rn(v.z, v.w);
    *reinterpret_cast<__half2*>(dst + (size_t)i * 4)     = h0;
    *reinterpret_cast<__half2*>(dst + (size_t)i * 4 + 2) = h1;
}

__global__ void k0_gates(
    const float* __restrict__ Wr, const float* __restrict__ Ww,
    const float* __restrict__ Wm)
{
    int row = blockIdx.x;       // 0..1023
    int n = threadIdx.x;        // 0..95
    float v;
    if (n < 32)      v = Wr[row * M_ + n];
    else if (n < 64) v = Ww[row * M_ + (n - 32)];
    else             v = Wm[row * M_ + (n - 64)];
    g_wg[row * 96 + n] = __float2half_rn(v);
}

// ============================================================
// K1: gates GEMM (32768 x 96) = X @ [Wr|Ww|Wm], fp16 tensor cores
// BM=128, BN=96, BK=32, 8 warps (4m x 2n), warp tile 32x48
// ============================================================
__device__ __forceinline__ void k1_copy(u32 sbase, int rowBase, int t, int k0)
{
#pragma unroll
    for (int u = 0; u < 2; u++) {
        int idx = t + u * 256;
        int row = idx >> 2;
        int c = idx & 3;
        const __half* g = g_xh + (size_t)(rowBase + row) * D_ + k0 + c * 8;
        cpa16(sbase + row * 80 + c * 16, g);
    }
#pragma unroll
    for (int u = 0; u < 2; u++) {
        int idx = t + u * 256;
        if (idx < 384) {
            int row = idx / 12;
            int c = idx % 12;
            const __half* g = g_wg + (size_t)(k0 + row) * 96 + c * 8;
            cpa16(sbase + A_BYT + row * 208 + c * 16, g);
        }
    }
}

__global__ void __launch_bounds__(256) k1_rwm(
    const float* __restrict__ br, const float* __restrict__ bw,
    const float* __restrict__ bm)
{
    __shared__ __align__(16) char sm1[2 * STG1];
    const int t = threadIdx.x;
    const int rowBase = blockIdx.x * 128;
    const int wid = t >> 5;
    const int lane = t & 31;
    const int wm = wid >> 1;
    const int wn = wid & 1;
    const u32 smBase = (u32)__cvta_generic_to_shared(sm1);

    float acc[2][6][4];
#pragma unroll
    for (int i = 0; i < 2; i++) {
#pragma unroll
        for (int j = 0; j < 6; j++) {
#pragma unroll
            for (int kq = 0; kq < 4; kq++) acc[i][j][kq] = 0.f;
        }
    }

    const int NS = 32;  // K = 1024
    k1_copy(smBase, rowBase, t, 0);
    cpa_commit();
    k1_copy(smBase + STG1, rowBase, t, 32);
    cpa_commit();
    cpa_wait1();
    __syncthreads();

    for (int s = 0; s < NS; s++) {
        u32 buf = smBase + (u32)(s & 1) * STG1;
#pragma unroll
        for (int kh = 0; kh < 2; kh++) {
            int kk = kh * 16;
            u32 a[2][4];
#pragma unroll
            for (int mt = 0; mt < 2; mt++) {
                int r = wm * 32 + mt * 16 + (lane & 15);
                int kc = kk + ((lane >> 4) << 3);
                ldsm_x4(a[mt], buf + (r * APADH + kc) * 2);
            }
            int krow = kk + (lane & 7) + ((lane >> 3) & 1) * 8;
#pragma unroll
            for (int nt = 0; nt < 6; nt++) {
                int nn = wn * 48 + nt * 8;
                u32 b[2];
                ldsm_x2t(b, buf + A_BYT + (krow * B1PADH + nn) * 2);
#pragma unroll
                for (int mt = 0; mt < 2; mt++) {
                    mma_f16(acc[mt][nt], a[mt], b);
                }
            }
        }
        __syncthreads();
        if (s + 2 < NS) {
            k1_copy(buf, rowBase, t, (s + 2) * 32);
            cpa_commit();
        }
        if (s + 1 < NS) {
            if (s + 2 < NS) cpa_wait1();
            else cpa_wait0();
            __syncthreads();
        }
    }

    // epilogue: bias + sigmoid, scatter to g_r/g_w/g_nm
#pragma unroll
    for (int mt = 0; mt < 2; mt++) {
#pragma unroll
        for (int nt = 0; nt < 6; nt++) {
            int n = wn * 48 + nt * 8 + (lane & 3) * 2;
            int row0 = rowBase + wm * 32 + mt * 16 + (lane >> 2);
#pragma unroll
            for (int half = 0; half < 2; half++) {
                int row = row0 + half * 8;
                float v0 = acc[mt][nt][half * 2 + 0];
                float v1 = acc[mt][nt][half * 2 + 1];
                float2 o;
                if (n < 32) {
                    o.x = 1.f / (1.f + expf(-(v0 + br[n])));
                    o.y = 1.f / (1.f + expf(-(v1 + br[n + 1])));
                    *reinterpret_cast<float2*>(&g_r[(size_t)row * M_ + n]) = o;
                } else if (n < 64) {
                    o.x = 1.f / (1.f + expf(-(v0 + bw[n - 32])));
                    o.y = 1.f / (1.f + expf(-(v1 + bw[n - 31])));
                    *reinterpret_cast<float2*>(&g_w[(size_t)row * M_ + n - 32]) = o;
                } else {
                    o.x = v0 + bm[n - 64];
                    o.y = v1 + bm[n - 63];
                    *reinterpret_cast<float2*>(&g_nm[(size_t)row * M_ + n - 64]) = o;
                }
            }
        }
    }
}

// ============================================================
// K2: Wq = Wp @ Wo_m  (32x1024)@(1024x1024), f32
// ============================================================
__global__ void __launch_bounds__(256) k2_wq(
    const float* __restrict__ Wp, const float* __restrict__ Wo)
{
    __shared__ float Ps[32][128];
    const int t = threadIdx.x;
    const int e = blockIdx.x * 128 + (t & 127);
    const int mg = t >> 7;
    float acc[16];
#pragma unroll
    for (int i = 0; i < 16; i++) acc[i] = 0.f;

    for (int d0 = 0; d0 < D_; d0 += 128) {
#pragma unroll
        for (int u = 0; u < 16; u++) {
            int idx = t + u * 256;
            Ps[idx >> 7][idx & 127] = Wp[(idx >> 7) * D_ + d0 + (idx & 127)];
        }
        __syncthreads();
        for (int dd = 0; dd < 128; dd++) {
            float wo = Wo[(size_t)(D_ + d0 + dd) * D_ + e];
#pragma unroll
            for (int i = 0; i < 16; i++)
                acc[i] += Ps[mg * 16 + i][dd] * wo;
        }
        __syncthreads();
    }
#pragma unroll
    for (int i = 0; i < 16; i++)
        g_wq[(mg * 16 + i) * D_ + e] = acc[i];
}

__global__ void k2_cvec(
    const float* __restrict__ bp, const float* __restrict__ Wo,
    const float* __restrict__ bo)
{
    int e = blockIdx.x * 256 + threadIdx.x;
    float acc = bo[e];
    for (int d = 0; d < D_; d++)
        acc += bp[d] * Wo[(size_t)(D_ + d) * D_ + e];
    g_cvec[e] = acc;
}

// ============================================================
// K3: chunked parallel scan of mem[t+1] = (1-w)*mem + w*nm
// ============================================================
__global__ void __launch_bounds__(256) k3a_chunk()
{
    int g = blockIdx.x * 256 + threadIdx.x;
    int m = g & 31;
    int c = (g >> 5) & (NC_ - 1);
    int b = g >> 11;
    size_t base = ((size_t)b * S_ + (size_t)c * CHUNK_) * M_ + m;
    float A = 1.f;
    float Bc = 0.f;
    for (int i = 0; i < CHUNK_; i++) {
        size_t idx = base + (size_t)i * M_;
        float wv = g_w[idx];
        float a = 1.f - wv;
        A = a * A;
        Bc = a * Bc + wv * g_nm[idx];
    }
    g_cA[g] = A;
    g_cB[g] = Bc;
}

__global__ void k3b_prefix()
{
    int t = threadIdx.x;
    int b = t >> 5;
    int m = t & 31;
    float mem = 0.f;
    for (int c = 0; c < NC_; c++) {
        int gi = (b * NC_ + c) * 32 + m;
        g_ms[gi] = mem;
        mem = g_cA[gi] * mem + g_cB[gi];
    }
}

__global__ void __launch_bounds__(256) k3c_emit()
{
    int g = blockIdx.x * 256 + threadIdx.x;
    int m = g & 31;
    int c = (g >> 5) & (NC_ - 1);
    int b = g >> 11;
    size_t base = ((size_t)b * S_ + (size_t)c * CHUNK_) * M_ + m;
    float mem = g_ms[g];
    for (int i = 0; i < CHUNK_; i++) {
        size_t idx = base + (size_t)i * M_;
        float rv = g_r[idx];
        float wv = g_w[idx];
        float nv = g_nm[idx];
        g_qh[idx] = __float2half_rn(rv * mem);
        mem = (1.f - wv) * mem + wv * nv;
    }
}

// ============================================================
// K4: out(32768,1024) = tanh([X|Q] @ [[Wo_x],[Wq]] + cvec), K=1056
// BM=128, BN=128, BK=32, 8 warps (4m x 2n), warp tile 32x64, fp16
// ============================================================
__device__ __forceinline__ void k4_copy(u32 sbase, int rowBase, int e0, int t, int k0)
{
#pragma unroll
    for (int u = 0; u < 2; u++) {
        int idx = t + u * 256;
        int row = idx >> 2;
        int c = idx & 3;
        const __half* g;
        if (k0 < 1024) g = g_xh + (size_t)(rowBase + row) * D_ + k0 + c * 8;
        else           g = g_qh + (size_t)(rowBase + row) * M_ + c * 8;
        cpa16(sbase + row * 80 + c * 16, g);
    }
#pragma unroll
    for (int u = 0; u < 2; u++) {
        int idx = t + u * 256;
        int row = idx >> 4;
        int c = idx & 15;
        const __half* g;
        if (k0 < 1024) g = g_woh + (size_t)(k0 + row) * D_ + e0 + c * 8;
        else           g = g_wqh + (size_t)row * D_ + e0 + c * 8;
        cpa16(sbase + A_BYT + row * 272 + c * 16, g);
    }
}

__global__ void __launch_bounds__(256) k4_gemm(float* __restrict__ out)
{
    __shared__ __align__(16) char sm4[2 * STG4];
    const int t = threadIdx.x;
    const int rowBase = blockIdx.y * 128;
    const int e0 = blockIdx.x * 128;
    const int wid = t >> 5;
    const int lane = t & 31;
    const int wm = wid >> 1;
    const int wn = wid & 1;
    const u32 smBase = (u32)__cvta_generic_to_shared(sm4);

    float acc[2][8][4];
#pragma unroll
    for (int i = 0; i < 2; i++) {
#pragma unroll
        for (int j = 0; j < 8; j++) {
#pragma unroll
            for (int kq = 0; kq < 4; kq++) acc[i][j][kq] = 0.f;
        }
    }

    const int NS = 33;  // K = 1056
    k4_copy(smBase, rowBase, e0, t, 0);
    cpa_commit();
    k4_copy(smBase + STG4, rowBase, e0, t, 32);
    cpa_commit();
    cpa_wait1();
    __syncthreads();

    for (int s = 0; s < NS; s++) {
        u32 buf = smBase + (u32)(s & 1) * STG4;
#pragma unroll
        for (int kh = 0; kh < 2; kh++) {
            int kk = kh * 16;
            u32 a[2][4];
#pragma unroll
            for (int mt = 0; mt < 2; mt++) {
                int r = wm * 32 + mt * 16 + (lane & 15);
                int kc = kk + ((lane >> 4) << 3);
                ldsm_x4(a[mt], buf + (r * APADH + kc) * 2);
            }
            int krow = kk + (lane & 7) + ((lane >> 3) & 1) * 8;
#pragma unroll
            for (int nt = 0; nt < 8; nt++) {
                int nn = wn * 64 + nt * 8;
                u32 b[2];
                ldsm_x2t(b, buf + A_BYT + (krow * B4PADH + nn) * 2);
#pragma unroll
                for (int mt = 0; mt < 2; mt++) {
                    mma_f16(acc[mt][nt], a[mt], b);
                }
            }
        }
        __syncthreads();
        if (s + 2 < NS) {
            k4_copy(buf, rowBase, e0, t, (s + 2) * 32);
            cpa_commit();
        }
        if (s + 1 < NS) {
            if (s + 2 < NS) cpa_wait1();
            else cpa_wait0();
            __syncthreads();
        }
    }

    // epilogue: + cvec, tanh
#pragma unroll
    for (int mt = 0; mt < 2; mt++) {
#pragma unroll
        for (int nt = 0; nt < 8; nt++) {
            int col = e0 + wn * 64 + nt * 8 + (lane & 3) * 2;
            float cv0 = g_cvec[col];
            float cv1 = g_cvec[col + 1];
            int row0 = rowBase + wm * 32 + mt * 16 + (lane >> 2);
#pragma unroll
            for (int half = 0; half < 2; half++) {
                int row = row0 + half * 8;
                float2 o;
                o.x = tanhf(acc[mt][nt][half * 2 + 0] + cv0);
                o.y = tanhf(acc[mt][nt][half * 2 + 1] + cv1);
                *reinterpret_cast<float2*>(&out[(size_t)row * D_ + col]) = o;
            }
        }
    }
}

// ============================================================
// launch
// ============================================================
extern "C" void kernel_launch(void* const* d_in, const int* in_sizes, int n_in,
                              void* d_out, int out_size)
{
    const float* x  = (const float*)d_in[0];
    const float* Wr = (const float*)d_in[1];
    const float* br = (const float*)d_in[2];
    const float* Ww = (const float*)d_in[3];
    const float* bw = (const float*)d_in[4];
    const float* Wm = (const float*)d_in[5];
    const float* bm = (const float*)d_in[6];
    const float* Wp = (const float*)d_in[7];
    const float* bp = (const float*)d_in[8];
    const float* Wo = (const float*)d_in[9];
    const float* bo = (const float*)d_in[10];
    float* out = (float*)d_out;

    __half* dx;
    __half* dwo;
    __half* dwq;
    cudaGetSymbolAddress((void**)&dx, g_xh);
    cudaGetSymbolAddress((void**)&dwo, g_woh);
    cudaGetSymbolAddress((void**)&dwq, g_wqh);

    float* dgwq;
    cudaGetSymbolAddress((void**)&dgwq, g_wq);

    // 0) fp16 conversions
    k0_f2h<<<(R_ * D_) / 1024, 256>>>(x, dx);            // X -> g_xh
    k0_f2h<<<(D_ * D_) / 1024, 256>>>(Wo, dwo);          // Wo_x -> g_woh
    k0_gates<<<D_, 96>>>(Wr, Ww, Wm);                    // pack gate weights

    // 1) gates GEMM (fp16 tensor cores)
    k1_rwm<<<R_ / 128, 256>>>(br, bw, bm);

    // 2) folded weights
    k2_wq<<<8, 256>>>(Wp, Wo);
    k2_cvec<<<4, 256>>>(bp, Wo, bo);
    k0_f2h<<<(M_ * D_) / 1024, 256>>>(dgwq, dwq);        // Wq -> g_wqh

    // 3) linear-recurrence scan (emits fp16 Q)
    k3a_chunk<<<(B_ * M_ * NC_) / 256, 256>>>();
    k3b_prefix<<<1, 256>>>();
    k3c_emit<<<(B_ * M_ * NC_) / 256, 256>>>();

    // 4) fused output GEMM + tanh (fp16 tensor cores)
    dim3 grid4(D_ / 128, R_ / 128);
    k4_gemm<<<grid4, 256>>>(out);
}

// round 7
// speedup vs baseline: 3.1973x; 1.0330x over previous
#include <cuda_runtime.h>
#include <cuda_fp16.h>
#include <math.h>

typedef unsigned int u32;

// Problem constants
#define B_   8
#define S_   4096
#define D_   1024
#define M_   32
#define R_   (B_*S_)      // 32768 rows
#define NC_  64
#define CHUNK_ 64
#define KP_  1056         // K for k4: [X(1024) | Q(32)]
#define NS4  33           // 1056 / 32 K-chunks

// -------- device scratch --------
__device__ float  g_r [R_*M_];
__device__ float  g_w [R_*M_];
__device__ float  g_nm[R_*M_];
__device__ float  g_wq[M_*D_];            // Wp @ Wo_m (f32)
__device__ float  g_cvec[D_];
__device__ float  g_cA[B_*NC_*M_];
__device__ float  g_cB[B_*NC_*M_];
__device__ float  g_ms[B_*NC_*M_];
__device__ __half g_xq[(size_t)R_*KP_];   // fp16 [X | Q]
__device__ __half g_wall[(size_t)KP_*D_]; // fp16 [Wo_x ; Wq], K-major rows of N=1024
__device__ __half g_wg[D_*96];            // fp16 packed [Wr|Ww|Wm]

// ---------------- helpers ----------------
__device__ __forceinline__ void mma_f16(float* c, const u32* a, const u32* b) {
    asm volatile(
        "mma.sync.aligned.m16n8k16.row.col.f32.f16.f16.f32 "
        "{%0,%1,%2,%3},{%4,%5,%6,%7},{%8,%9},{%0,%1,%2,%3};\n"
        : "+f"(c[0]), "+f"(c[1]), "+f"(c[2]), "+f"(c[3])
        : "r"(a[0]), "r"(a[1]), "r"(a[2]), "r"(a[3]), "r"(b[0]), "r"(b[1]));
}
__device__ __forceinline__ void ldsm_x4(u32* r, u32 addr) {
    asm volatile("ldmatrix.sync.aligned.m8n8.x4.shared.b16 {%0,%1,%2,%3},[%4];"
        : "=r"(r[0]), "=r"(r[1]), "=r"(r[2]), "=r"(r[3]) : "r"(addr));
}
__device__ __forceinline__ void ldsm_x2t(u32* r, u32 addr) {
    asm volatile("ldmatrix.sync.aligned.m8n8.x2.trans.shared.b16 {%0,%1},[%2];"
        : "=r"(r[0]), "=r"(r[1]) : "r"(addr));
}
__device__ __forceinline__ void ldsm_x4t(u32* r, u32 addr) {
    asm volatile("ldmatrix.sync.aligned.m8n8.x4.trans.shared.b16 {%0,%1,%2,%3},[%4];"
        : "=r"(r[0]), "=r"(r[1]), "=r"(r[2]), "=r"(r[3]) : "r"(addr));
}
__device__ __forceinline__ void cpa16(u32 saddr, const void* gptr) {
    asm volatile("cp.async.cg.shared.global [%0], [%1], 16;" :: "r"(saddr), "l"(gptr));
}
__device__ __forceinline__ void cpa_commit() { asm volatile("cp.async.commit_group;"); }
__device__ __forceinline__ void cpa_wait1()  { asm volatile("cp.async.wait_group 1;"); }
__device__ __forceinline__ void cpa_wait0()  { asm volatile("cp.async.wait_group 0;"); }

// ============================================================
// K0: conversion / packing kernels
// ============================================================
// X (f32 [R][1024]) -> g_xq fp16 rows with stride KP_
__global__ void __launch_bounds__(256) k0_x(const float* __restrict__ x)
{
    int idx = blockIdx.x * 256 + threadIdx.x;     // one float4
    int r = idx >> 8;
    int c4 = idx & 255;
    float4 v = *reinterpret_cast<const float4*>(x + (size_t)idx * 4);
    __half2 h0 = __floats2half2_rn(v.x, v.y);
    __half2 h1 = __floats2half2_rn(v.z, v.w);
    __half* dst = g_xq + (size_t)r * KP_ + c4 * 4;
    *reinterpret_cast<__half2*>(dst)     = h0;
    *reinterpret_cast<__half2*>(dst + 2) = h1;
}

// generic contiguous f32 -> f16
__global__ void __launch_bounds__(256) k0_f2h(
    const float* __restrict__ src, __half* __restrict__ dst)
{
    int i = blockIdx.x * 256 + threadIdx.x;
    float4 v = *reinterpret_cast<const float4*>(src + (size_t)i * 4);
    __half2 h0 = __floats2half2_rn(v.x, v.y);
    __half2 h1 = __floats2half2_rn(v.z, v.w);
    *reinterpret_cast<__half2*>(dst + (size_t)i * 4)     = h0;
    *reinterpret_cast<__half2*>(dst + (size_t)i * 4 + 2) = h1;
}

__global__ void k0_gates(
    const float* __restrict__ Wr, const float* __restrict__ Ww,
    const float* __restrict__ Wm)
{
    int row = blockIdx.x;
    int n = threadIdx.x;
    float v;
    if (n < 32)      v = Wr[row * M_ + n];
    else if (n < 64) v = Ww[row * M_ + (n - 32)];
    else             v = Wm[row * M_ + (n - 64)];
    g_wg[row * 96 + n] = __float2half_rn(v);
}

// ============================================================
// K1: gates GEMM (32768 x 96) = X @ [Wr|Ww|Wm], mma.sync fp16
// BM=128, BN=96, BK=32, 8 warps (4m x 2n), warp tile 32x48
// ============================================================
#define APADH   40
#define A_BYT   10240
#define B1PADH  104
#define STG1    16896

__device__ __forceinline__ void k1_copy(u32 sbase, int rowBase, int t, int k0)
{
#pragma unroll
    for (int u = 0; u < 2; u++) {
        int idx = t + u * 256;
        int row = idx >> 2;
        int c = idx & 3;
        const __half* g = g_xq + (size_t)(rowBase + row) * KP_ + k0 + c * 8;
        cpa16(sbase + row * 80 + c * 16, g);
    }
#pragma unroll
    for (int u = 0; u < 2; u++) {
        int idx = t + u * 256;
        if (idx < 384) {
            int row = idx / 12;
            int c = idx % 12;
            const __half* g = g_wg + (size_t)(k0 + row) * 96 + c * 8;
            cpa16(sbase + A_BYT + row * 208 + c * 16, g);
        }
    }
}

__global__ void __launch_bounds__(256) k1_rwm(
    const float* __restrict__ br, const float* __restrict__ bw,
    const float* __restrict__ bm)
{
    __shared__ __align__(16) char sm1[2 * STG1];
    const int t = threadIdx.x;
    const int rowBase = blockIdx.x * 128;
    const int wid = t >> 5;
    const int lane = t & 31;
    const int wm = wid >> 1;
    const int wn = wid & 1;
    const u32 smBase = (u32)__cvta_generic_to_shared(sm1);

    float acc[2][6][4];
#pragma unroll
    for (int i = 0; i < 2; i++) {
#pragma unroll
        for (int j = 0; j < 6; j++) {
#pragma unroll
            for (int kq = 0; kq < 4; kq++) acc[i][j][kq] = 0.f;
        }
    }

    const int NS = 32;
    k1_copy(smBase, rowBase, t, 0);
    cpa_commit();
    k1_copy(smBase + STG1, rowBase, t, 32);
    cpa_commit();
    cpa_wait1();
    __syncthreads();

    for (int s = 0; s < NS; s++) {
        u32 buf = smBase + (u32)(s & 1) * STG1;
#pragma unroll
        for (int kh = 0; kh < 2; kh++) {
            int kk = kh * 16;
            u32 a[2][4];
#pragma unroll
            for (int mt = 0; mt < 2; mt++) {
                int r = wm * 32 + mt * 16 + (lane & 15);
                int kc = kk + ((lane >> 4) << 3);
                ldsm_x4(a[mt], buf + (r * APADH + kc) * 2);
            }
            int krow = kk + (lane & 7) + ((lane >> 3) & 1) * 8;
#pragma unroll
            for (int nt = 0; nt < 6; nt++) {
                int nn = wn * 48 + nt * 8;
                u32 b[2];
                ldsm_x2t(b, buf + A_BYT + (krow * B1PADH + nn) * 2);
#pragma unroll
                for (int mt = 0; mt < 2; mt++) {
                    mma_f16(acc[mt][nt], a[mt], b);
                }
            }
        }
        __syncthreads();
        if (s + 2 < NS) {
            k1_copy(buf, rowBase, t, (s + 2) * 32);
            cpa_commit();
        }
        if (s + 1 < NS) {
            if (s + 2 < NS) cpa_wait1();
            else cpa_wait0();
            __syncthreads();
        }
    }

#pragma unroll
    for (int mt = 0; mt < 2; mt++) {
#pragma unroll
        for (int nt = 0; nt < 6; nt++) {
            int n = wn * 48 + nt * 8 + (lane & 3) * 2;
            int row0 = rowBase + wm * 32 + mt * 16 + (lane >> 2);
#pragma unroll
            for (int half = 0; half < 2; half++) {
                int row = row0 + half * 8;
                float v0 = acc[mt][nt][half * 2 + 0];
                float v1 = acc[mt][nt][half * 2 + 1];
                float2 o;
                if (n < 32) {
                    o.x = 1.f / (1.f + expf(-(v0 + br[n])));
                    o.y = 1.f / (1.f + expf(-(v1 + br[n + 1])));
                    *reinterpret_cast<float2*>(&g_r[(size_t)row * M_ + n]) = o;
                } else if (n < 64) {
                    o.x = 1.f / (1.f + expf(-(v0 + bw[n - 32])));
                    o.y = 1.f / (1.f + expf(-(v1 + bw[n - 31])));
                    *reinterpret_cast<float2*>(&g_w[(size_t)row * M_ + n - 32]) = o;
                } else {
                    o.x = v0 + bm[n - 64];
                    o.y = v1 + bm[n - 63];
                    *reinterpret_cast<float2*>(&g_nm[(size_t)row * M_ + n - 64]) = o;
                }
            }
        }
    }
}

// ============================================================
// K2: Wq = Wp @ Wo_m  (32x1024)@(1024x1024), f32
// ============================================================
__global__ void __launch_bounds__(256) k2_wq(
    const float* __restrict__ Wp, const float* __restrict__ Wo)
{
    __shared__ float Ps[32][128];
    const int t = threadIdx.x;
    const int e = blockIdx.x * 128 + (t & 127);
    const int mg = t >> 7;
    float acc[16];
#pragma unroll
    for (int i = 0; i < 16; i++) acc[i] = 0.f;

    for (int d0 = 0; d0 < D_; d0 += 128) {
#pragma unroll
        for (int u = 0; u < 16; u++) {
            int idx = t + u * 256;
            Ps[idx >> 7][idx & 127] = Wp[(idx >> 7) * D_ + d0 + (idx & 127)];
        }
        __syncthreads();
        for (int dd = 0; dd < 128; dd++) {
            float wo = Wo[(size_t)(D_ + d0 + dd) * D_ + e];
#pragma unroll
            for (int i = 0; i < 16; i++)
                acc[i] += Ps[mg * 16 + i][dd] * wo;
        }
        __syncthreads();
    }
#pragma unroll
    for (int i = 0; i < 16; i++)
        g_wq[(mg * 16 + i) * D_ + e] = acc[i];
}

__global__ void k2_cvec(
    const float* __restrict__ bp, const float* __restrict__ Wo,
    const float* __restrict__ bo)
{
    int e = blockIdx.x * 256 + threadIdx.x;
    float acc = bo[e];
    for (int d = 0; d < D_; d++)
        acc += bp[d] * Wo[(size_t)(D_ + d) * D_ + e];
    g_cvec[e] = acc;
}

// ============================================================
// K3: chunked parallel scan of mem[t+1] = (1-w)*mem + w*nm
// ============================================================
__global__ void __launch_bounds__(256) k3a_chunk()
{
    int g = blockIdx.x * 256 + threadIdx.x;
    int m = g & 31;
    int c = (g >> 5) & (NC_ - 1);
    int b = g >> 11;
    size_t base = ((size_t)b * S_ + (size_t)c * CHUNK_) * M_ + m;
    float A = 1.f;
    float Bc = 0.f;
    for (int i = 0; i < CHUNK_; i++) {
        size_t idx = base + (size_t)i * M_;
        float wv = g_w[idx];
        float a = 1.f - wv;
        A = a * A;
        Bc = a * Bc + wv * g_nm[idx];
    }
    g_cA[g] = A;
    g_cB[g] = Bc;
}

__global__ void k3b_prefix()
{
    int t = threadIdx.x;
    int b = t >> 5;
    int m = t & 31;
    float mem = 0.f;
    for (int c = 0; c < NC_; c++) {
        int gi = (b * NC_ + c) * 32 + m;
        g_ms[gi] = mem;
        mem = g_cA[gi] * mem + g_cB[gi];
    }
}

__global__ void __launch_bounds__(256) k3c_emit()
{
    int g = blockIdx.x * 256 + threadIdx.x;
    int m = g & 31;
    int c = (g >> 5) & (NC_ - 1);
    int b = g >> 11;
    int row0 = b * S_ + c * CHUNK_;
    float mem = g_ms[g];
    for (int i = 0; i < CHUNK_; i++) {
        int row = row0 + i;
        size_t idx = (size_t)row * M_ + m;
        float rv = g_r[idx];
        float wv = g_w[idx];
        float nv = g_nm[idx];
        g_xq[(size_t)row * KP_ + 1024 + m] = __float2half_rn(rv * mem);
        mem = (1.f - wv) * mem + wv * nv;
    }
}

// ============================================================
// K4: out(32768,1024) = tanh( g_xq @ g_wall + cvec ), K=1056
// CTA 128x128, 128 threads (4 warps, 2m x 2n), warp tile 64x64
// ============================================================
#define B4PADH  136
#define B4_BYT  8704
#define STG4    18944      // A_BYT + B4_BYT

__device__ __forceinline__ void k4_copy(u32 sbase, int rowBase, int e0, int t, int k0)
{
#pragma unroll
    for (int u = 0; u < 4; u++) {
        int idx = t + u * 128;
        int row = idx >> 2;
        int c = idx & 3;
        cpa16(sbase + row * 80 + c * 16,
              g_xq + (size_t)(rowBase + row) * KP_ + k0 + c * 8);
    }
#pragma unroll
    for (int u = 0; u < 4; u++) {
        int idx = t + u * 128;
        int row = idx >> 4;
        int c = idx & 15;
        cpa16(sbase + A_BYT + row * 272 + c * 16,
              g_wall + (size_t)(k0 + row) * D_ + e0 + c * 8);
    }
}

__global__ void __launch_bounds__(128) k4_mm(float* __restrict__ out)
{
    __shared__ __align__(16) char sm4[2 * STG4];
    const int t = threadIdx.x;
    const int rowBase = blockIdx.y * 128;
    const int e0 = blockIdx.x * 128;
    const int wid = t >> 5;
    const int lane = t & 31;
    const int wm = wid >> 1;     // 0..1 -> rows wm*64
    const int wn = wid & 1;      // 0..1 -> cols wn*64
    const u32 smBase = (u32)__cvta_generic_to_shared(sm4);

    float acc[4][8][4];
#pragma unroll
    for (int i = 0; i < 4; i++) {
#pragma unroll
        for (int j = 0; j < 8; j++) {
#pragma unroll
            for (int kq = 0; kq < 4; kq++) acc[i][j][kq] = 0.f;
        }
    }

    k4_copy(smBase, rowBase, e0, t, 0);
    cpa_commit();
    k4_copy(smBase + STG4, rowBase, e0, t, 32);
    cpa_commit();
    cpa_wait1();
    __syncthreads();

    for (int s = 0; s < NS4; s++) {
        u32 buf = smBase + (u32)(s & 1) * STG4;
#pragma unroll
        for (int kh = 0; kh < 2; kh++) {
            int kk = kh * 16;
            u32 a[4][4];
#pragma unroll
            for (int mt = 0; mt < 4; mt++) {
                int r = wm * 64 + mt * 16 + (lane & 15);
                int kc = kk + ((lane >> 4) << 3);
                ldsm_x4(a[mt], buf + (r * APADH + kc) * 2);
            }
            int krow = kk + (lane & 7) + ((lane >> 3) & 1) * 8;
            int ncol = ((lane >> 4) << 3);
#pragma unroll
            for (int nt4 = 0; nt4 < 4; nt4++) {
                int nn = wn * 64 + nt4 * 16;
                u32 b[4];
                ldsm_x4t(b, buf + A_BYT + (krow * B4PADH + nn + ncol) * 2);
#pragma unroll
                for (int mt = 0; mt < 4; mt++) {
                    mma_f16(acc[mt][2 * nt4],     a[mt], b);
                    mma_f16(acc[mt][2 * nt4 + 1], a[mt], b + 2);
                }
            }
        }
        __syncthreads();
        if (s + 2 < NS4) {
            k4_copy(buf, rowBase, e0, t, (s + 2) * 32);
            cpa_commit();
        }
        if (s + 1 < NS4) {
            if (s + 2 < NS4) cpa_wait1();
            else cpa_wait0();
            __syncthreads();
        }
    }

    // epilogue: + cvec, tanh
#pragma unroll
    for (int mt = 0; mt < 4; mt++) {
#pragma unroll
        for (int nt = 0; nt < 8; nt++) {
            int col = e0 + wn * 64 + nt * 8 + (lane & 3) * 2;
            float cv0 = g_cvec[col];
            float cv1 = g_cvec[col + 1];
            int row0 = rowBase + wm * 64 + mt * 16 + (lane >> 2);
#pragma unroll
            for (int half = 0; half < 2; half++) {
                int row = row0 + half * 8;
                float2 o;
                o.x = tanhf(acc[mt][nt][half * 2 + 0] + cv0);
                o.y = tanhf(acc[mt][nt][half * 2 + 1] + cv1);
                *reinterpret_cast<float2*>(&out[(size_t)row * D_ + col]) = o;
            }
        }
    }
}

// ============================================================
// launch
// ============================================================
extern "C" void kernel_launch(void* const* d_in, const int* in_sizes, int n_in,
                              void* d_out, int out_size)
{
    const float* x  = (const float*)d_in[0];
    const float* Wr = (const float*)d_in[1];
    const float* br = (const float*)d_in[2];
    const float* Ww = (const float*)d_in[3];
    const float* bw = (const float*)d_in[4];
    const float* Wm = (const float*)d_in[5];
    const float* bm = (const float*)d_in[6];
    const float* Wp = (const float*)d_in[7];
    const float* bp = (const float*)d_in[8];
    const float* Wo = (const float*)d_in[9];
    const float* bo = (const float*)d_in[10];
    float* out = (float*)d_out;

    __half* dwall;
    cudaGetSymbolAddress((void**)&dwall, g_wall);
    float* dgwq;
    cudaGetSymbolAddress((void**)&dgwq, g_wq);

    // 0) pack fp16 activation + weight buffers
    k0_x<<<(R_ * (D_ / 4)) / 256, 256>>>(x);            // X -> g_xq[:, :1024]
    k0_f2h<<<(D_ * D_) / 1024, 256>>>(Wo, dwall);       // Wo_x -> g_wall rows 0..1023
    k0_gates<<<D_, 96>>>(Wr, Ww, Wm);

    // 1) gates GEMM (mma.sync fp16)
    k1_rwm<<<R_ / 128, 256>>>(br, bw, bm);

    // 2) folded weights
    k2_wq<<<8, 256>>>(Wp, Wo);
    k2_cvec<<<4, 256>>>(bp, Wo, bo);
    k0_f2h<<<(M_ * D_) / 1024, 256>>>(dgwq, dwall + (size_t)1024 * D_); // Wq rows

    // 3) linear-recurrence scan (emits fp16 Q into g_xq)
    k3a_chunk<<<(B_ * M_ * NC_) / 256, 256>>>();
    k3b_prefix<<<1, 256>>>();
    k3c_emit<<<(B_ * M_ * NC_) / 256, 256>>>();

    // 4) output GEMM + tanh (mma.sync fp16, 64x64 warp tiles)
    dim3 grid4(D_ / 128, R_ / 128);
    k4_mm<<<grid4, 128>>>(out);
}